// round 13
// baseline (speedup 1.0000x reference)
#include <cuda_runtime.h>
#include <math.h>

// GEBLNet fused kernel, round 13 = round-9 winner byte-identical,
// EXCEPT __launch_bounds__(160,5) -> (160,6).  Single-variable experiment:
// tests the latency-bound hypothesis (occupancy is the binding constraint).

#define U    12
#define S1   13
#define S2   25
#define NB1  6
#define NB2  12
#define T1   (U*S1)      // 156
#define T2   (U*S2)      // 300
#define NT   160
#define NPTF 180

typedef unsigned long long u64;

__device__ float2 g_A1[NB1*T1], g_C1[T1];
__device__ float2 g_A2[NB2*T2], g_C2[T2];
__device__ float4 g_E1[NB1*T1];            // {er, -er, -ei, ei}  (signs precomputed)
__device__ float4 g_E2[NB2*T2];

__device__ __forceinline__ u64 pk(float lo, float hi) {
    u64 r; asm("mov.b64 %0,{%1,%2};" : "=l"(r) : "f"(lo), "f"(hi)); return r;
}
__device__ __forceinline__ void fma2(u64& d, u64 a, u64 b) {
    asm("fma.rn.f32x2 %0,%1,%2,%0;" : "+l"(d) : "l"(a), "l"(b));
}
__device__ __forceinline__ float2 up(u64 a) {
    float2 f; asm("mov.b64 {%0,%1},%2;" : "=f"(f.x), "=f"(f.y) : "l"(a)); return f;
}

__global__ void prep_w(const float* __restrict__ w1, const float* __restrict__ w2)
{
    int t = blockIdx.x * blockDim.x + threadIdx.x;
    if (t < T1) {
        const float* b = w1 + (size_t)t * S1 * 2;
        for (int w = 0; w < NB1; w++) {
            g_A1[w*T1 + t] = make_float2(b[2*w], b[2*w + 1]);
            float er = b[2*(NB1+w)], ei = b[2*(NB1+w) + 1];
            g_E1[w*T1 + t] = make_float4(er, -er, -ei, ei);
        }
        g_C1[t] = make_float2(b[2*(2*NB1)], b[2*(2*NB1) + 1]);
    }
    if (t < T2) {
        const float* b = w2 + (size_t)t * S2 * 2;
        for (int w = 0; w < NB2; w++) {
            g_A2[w*T2 + t] = make_float2(b[2*w], b[2*w + 1]);
            float er = b[2*(NB2+w)], ei = b[2*(NB2+w) + 1];
            g_E2[w*T2 + t] = make_float4(er, -er, -ei, ei);
        }
        g_C2[t] = make_float2(b[2*(2*NB2)], b[2*(2*NB2) + 1]);
    }
}

// C[u,v] = sum_w a_w*W[w] + sum_w e_w*W[w]^H + c*I, single accumulator:
//   acc[(i,k)] += {ar,ar}.b[(i,k)] + {ai,ai}.bs[(i,k)]
//              + {er,-er}.b[(k,i)] + {-ei,ei}.bs[(k,i)]
// Element order: diagonals {0,4,8} then symmetric pairs (1,3),(2,6),(5,7),
// so at most 2 bp values are live at a time.
template<int S, int NB, int TPT>
__device__ __forceinline__ void stage_c(const float2* __restrict__ gA,
                                        const float4* __restrict__ gE,
                                        const float2* __restrict__ gC,
                                        const ulonglong2* __restrict__ sWp,
                                        u64* __restrict__ sC, int tid)
{
    const int T = U * S;
    const int H = T / TPT;
    if (tid < H) {
        u64 acc[TPT][9];
#pragma unroll
        for (int t = 0; t < TPT; t++)
#pragma unroll
            for (int e = 0; e < 9; e++) acc[t][e] = 0ull;

#pragma unroll
        for (int w = 0; w < NB; ++w) {
            u64 ar[TPT], ai[TPT], er[TPT], ei[TPT];
#pragma unroll
            for (int t = 0; t < TPT; t++) {
                int task = tid + t * H;
                float2 aw = __ldg(gA + w*T + task);
                float4 ef = __ldg(gE + w*T + task);
                ar[t] = pk(aw.x, aw.x); ai[t] = pk(aw.y, aw.y);
                er[t] = pk(ef.x, ef.y); ei[t] = pk(ef.z, ef.w);
            }
            const ulonglong2* wp = sWp + w*9;
            // diagonal elements (e == et): 1 bp live
#pragma unroll
            for (int d = 0; d < 3; d++) {
                const int e = d*4;                 // 0, 4, 8
                ulonglong2 bp = wp[e];
#pragma unroll
                for (int t = 0; t < TPT; t++) {
                    fma2(acc[t][e], ar[t], bp.x);
                    fma2(acc[t][e], ai[t], bp.y);
                    fma2(acc[t][e], er[t], bp.x);
                    fma2(acc[t][e], ei[t], bp.y);
                }
            }
            // symmetric pairs (e, et): 2 bp live
#pragma unroll
            for (int q = 0; q < 3; q++) {
                const int e  = (q == 0) ? 1 : (q == 1) ? 2 : 5;
                const int et = (q == 0) ? 3 : (q == 1) ? 6 : 7;
                ulonglong2 bpE = wp[e];
                ulonglong2 bpT = wp[et];
#pragma unroll
                for (int t = 0; t < TPT; t++) {
                    fma2(acc[t][e],  ar[t], bpE.x);
                    fma2(acc[t][e],  ai[t], bpE.y);
                    fma2(acc[t][e],  er[t], bpT.x);
                    fma2(acc[t][e],  ei[t], bpT.y);
                    fma2(acc[t][et], ar[t], bpT.x);
                    fma2(acc[t][et], ai[t], bpT.y);
                    fma2(acc[t][et], er[t], bpE.x);
                    fma2(acc[t][et], ei[t], bpE.y);
                }
            }
        }
        const u64 one2 = pk(1.0f, 1.0f);
#pragma unroll
        for (int t = 0; t < TPT; t++) {
            int task = tid + t * H;
            float2 cw = __ldg(gC + task);
            u64 cc = pk(cw.x, cw.y);
            fma2(acc[t][0], one2, cc);
            fma2(acc[t][4], one2, cc);
            fma2(acc[t][8], one2, cc);
#pragma unroll
            for (int e = 0; e < 9; e++) sC[e*T + task] = acc[t][e];
        }
    }
}

// wout[u](i,k) = sum_{v<NB} W[v](i,:)C[u,v](:,k)
//             + sum_{v<NB} W[v]^H(i,:)C[u,NB+v](:,k) + C[u,2NB](i,k)
template<int S, int NB>
__device__ __forceinline__ void stage_m(const ulonglong2* __restrict__ sWp,
                                        const u64* __restrict__ sC,
                                        u64* __restrict__ sM, int tid)
{
    const int T = U * S;
    if (tid < U * 9) {
        int u = tid / 9, e = tid % 9;
        int i = e / 3, k = e % 3;
        u64 a1 = 0ull, a2 = 0ull, a2c = 0ull;
        const u64* Cu = sC + u * S;
#pragma unroll
        for (int v = 0; v < NB; ++v) {
#pragma unroll
            for (int j = 0; j < 3; ++j) {
                float2 b = up(sWp[v*9 + i*3 + j].x);
                u64 c = Cu[(j*3 + k)*T + v];
                fma2(a1, pk(b.x, b.x), c);
                fma2(a2, pk(b.y, b.y), c);
            }
        }
#pragma unroll
        for (int v = 0; v < NB; ++v) {
#pragma unroll
            for (int j = 0; j < 3; ++j) {
                float2 b = up(sWp[v*9 + j*3 + i].x);
                u64 c = Cu[(j*3 + k)*T + NB + v];
                fma2(a1,  pk(b.x, b.x), c);
                fma2(a2c, pk(b.y, b.y), c);
            }
        }
        float2 p = up(a1), q = up(a2), qc = up(a2c);
        float2 ci = up(Cu[(i*3 + k)*T + 2*NB]);
        sM[u*9 + e] = pk(p.x - q.y + qc.y + ci.x,
                         p.y + q.x - qc.x + ci.y);
    }
}

__global__ __launch_bounds__(NT, 6)
void gebl_kernel(const float* __restrict__ x,
                 const float* __restrict__ dw,
                 const float* __restrict__ db,
                 float* __restrict__ out)
{
    __shared__ __align__(16) ulonglong2 sWp[NB2 * 9];   // 1728 B
    __shared__ u64   sC[9 * T2];                        // 21600 B
    __shared__ u64   sM[U * 9];                         // 864 B
    __shared__ float sTrRe[U], sTrIm[U], sAbs[U], sScale[U];
    __shared__ float sNormInv;

    const int tid   = threadIdx.x;
    const int point = blockIdx.x;
    const float2* xp = reinterpret_cast<const float2*>(x + (size_t)point * NPTF) + 4 * 9;

    // ---- Build base W1 ----
    if (tid < NB1 * 9) {
        float2 v = __ldg(xp + tid);
        sWp[tid] = make_ulonglong2(pk(v.x, v.y), pk(-v.y, v.x));
    }
    __syncthreads();

    // ---- Layer 1 (1 task/thread) ----
    stage_c<S1, NB1, 1>(g_A1, g_E1, g_C1, sWp, sC, tid);
    __syncthreads();
    stage_m<S1, NB1>(sWp, sC, sM, tid);
    __syncthreads();

    if (tid < U) {
        const u64* m = sM + tid*9;
        float2 t0 = up(m[0]), t4 = up(m[4]), t8 = up(m[8]);
        float trRe = t0.x + t4.x + t8.x;
        float trIm = t0.y + t4.y + t8.y;
        float t = fmaxf(trRe, 0.0f);
        sAbs[tid]   = t * sqrtf(trRe*trRe + trIm*trIm);
        sScale[tid] = t;
    }
    __syncthreads();
    if (tid == 0) {
        float s = 0.f;
#pragma unroll
        for (int u = 0; u < U; u++) s += sAbs[u];
        sNormInv = 1.0f / fmaxf(s * (1.0f / U), 0.001f);
    }
    __syncthreads();

    // ---- Build base W2 ----
    if (tid < U * 9) {
        int ch = tid / 9;
        float s = sScale[ch] * sNormInv;
        float2 m = up(sM[tid]);
        sWp[tid] = make_ulonglong2(pk(s*m.x, s*m.y), pk(-s*m.y, s*m.x));
    }
    __syncthreads();

    // ---- Layer 2 (2 tasks/thread) ----
    stage_c<S2, NB2, 2>(g_A2, g_E2, g_C2, sWp, sC, tid);
    __syncthreads();
    stage_m<S2, NB2>(sWp, sC, sM, tid);
    __syncthreads();

    // ---- Layer-2 scalars + head ----
    if (tid < U) {
        const u64* m = sM + tid*9;
        float2 t0 = up(m[0]), t4 = up(m[4]), t8 = up(m[8]);
        float trRe = t0.x + t4.x + t8.x;
        float trIm = t0.y + t4.y + t8.y;
        float t = fmaxf(trRe, 0.0f);
        sTrRe[tid]  = trRe;
        sTrIm[tid]  = trIm;
        sAbs[tid]   = t * sqrtf(trRe*trRe + trIm*trIm);
        sScale[tid] = t;
    }
    __syncthreads();
    if (tid == 0) {
        float s = 0.f;
#pragma unroll
        for (int u = 0; u < U; u++) s += sAbs[u];
        float inv_norm = 1.0f / fmaxf(s * (1.0f / U), 0.001f);
        float o = __ldg(&db[0]);
#pragma unroll
        for (int u = 0; u < U; u++) {
            float sc = sScale[u] * inv_norm * (1.0f / 3.0f);
            o = fmaf(sc * sTrRe[u], __ldg(&dw[2*u]),     o);
            o = fmaf(sc * sTrIm[u], __ldg(&dw[2*u + 1]), o);
        }
        out[point] = o;
    }
}

extern "C" void kernel_launch(void* const* d_in, const int* in_sizes, int n_in,
                              void* d_out, int out_size)
{
    const float* x  = (const float*)d_in[0];
    const float* w1 = (const float*)d_in[1];
    const float* w2 = (const float*)d_in[2];
    const float* dw = (const float*)d_in[3];
    const float* db = (const float*)d_in[4];
    float* out = (float*)d_out;

    int points = in_sizes[0] / NPTF;   // 8192

    prep_w<<<1, 320>>>(w1, w2);
    gebl_kernel<<<points, NT>>>(x, dw, db, out);
}

// round 14
// speedup vs baseline: 1.5621x; 1.5621x over previous
#include <cuda_runtime.h>
#include <math.h>

// GEBLNet fused kernel, round 14: TRACE-ONLY LAYER 2.
// tr(w_out2[u]) = sum_{v<=w} gtilde[u,p] * t[p],  t[p] = tr(W2[v] W2[w]) (symmetric).
// Layer 1 is the round-9 winner verbatim. Layer-2 full-matrix stages are GONE.

#define U    12
#define S1   13
#define S2   25
#define NB1  6
#define T1   (U*S1)      // 156
#define NT   160
#define NPTF 180
#define NPAIR 325        // S2*(S2+1)/2

typedef unsigned long long u64;

__device__ float2 g_A1[NB1*T1], g_C1[T1];
__device__ float4 g_E1[NB1*T1];            // {er, -er, -ei, ei}
__device__ float2 g_T2[U*NPAIR];           // folded layer-2 weights  gtilde[u][p]
__device__ int    g_pv[NPAIR], g_pw[NPAIR];

__device__ __forceinline__ u64 pk(float lo, float hi) {
    u64 r; asm("mov.b64 %0,{%1,%2};" : "=l"(r) : "f"(lo), "f"(hi)); return r;
}
__device__ __forceinline__ void fma2(u64& d, u64 a, u64 b) {
    asm("fma.rn.f32x2 %0,%1,%2,%0;" : "+l"(d) : "l"(a), "l"(b));
}
__device__ __forceinline__ float2 up(u64 a) {
    float2 f; asm("mov.b64 {%0,%1},%2;" : "=f"(f.x), "=f"(f.y) : "l"(a)); return f;
}

__global__ void prep_w(const float* __restrict__ w1, const float* __restrict__ w2)
{
    int n = blockIdx.x * blockDim.x + threadIdx.x;
    if (n < T1) {
        const float* b = w1 + (size_t)n * S1 * 2;
        for (int w = 0; w < NB1; w++) {
            g_A1[w*T1 + n] = make_float2(b[2*w], b[2*w + 1]);
            float er = b[2*(NB1+w)], ei = b[2*(NB1+w) + 1];
            g_E1[w*T1 + n] = make_float4(er, -er, -ei, ei);
        }
        g_C1[n] = make_float2(b[2*(2*NB1)], b[2*(2*NB1) + 1]);
    }
    if (n < U * NPAIR) {
        int u = n / NPAIR, p = n % NPAIR;
        int pp = p, v = 0;
        while (pp >= S2 - v) { pp -= S2 - v; v++; }
        int w = v + pp;
        const float* b1 = w2 + (((size_t)u*S2 + v)*S2 + w) * 2;
        float gr = b1[0], gi = b1[1];
        if (v != w) {
            const float* b2 = w2 + (((size_t)u*S2 + w)*S2 + v) * 2;
            gr += b2[0]; gi += b2[1];
        }
        g_T2[u*NPAIR + p] = make_float2(gr, gi);
        if (u == 0) { g_pv[p] = v; g_pw[p] = w; }
    }
}

// ---------------- Layer 1 (round-9 winner, verbatim) ----------------

template<int S, int NB, int TPT>
__device__ __forceinline__ void stage_c(const float2* __restrict__ gA,
                                        const float4* __restrict__ gE,
                                        const float2* __restrict__ gC,
                                        const ulonglong2* __restrict__ sWp,
                                        u64* __restrict__ sC, int tid)
{
    const int T = U * S;
    const int H = T / TPT;
    if (tid < H) {
        u64 acc[TPT][9];
#pragma unroll
        for (int t = 0; t < TPT; t++)
#pragma unroll
            for (int e = 0; e < 9; e++) acc[t][e] = 0ull;

#pragma unroll
        for (int w = 0; w < NB; ++w) {
            u64 ar[TPT], ai[TPT], er[TPT], ei[TPT];
#pragma unroll
            for (int t = 0; t < TPT; t++) {
                int task = tid + t * H;
                float2 aw = __ldg(gA + w*T + task);
                float4 ef = __ldg(gE + w*T + task);
                ar[t] = pk(aw.x, aw.x); ai[t] = pk(aw.y, aw.y);
                er[t] = pk(ef.x, ef.y); ei[t] = pk(ef.z, ef.w);
            }
            const ulonglong2* wp = sWp + w*9;
#pragma unroll
            for (int d = 0; d < 3; d++) {
                const int e = d*4;
                ulonglong2 bp = wp[e];
#pragma unroll
                for (int t = 0; t < TPT; t++) {
                    fma2(acc[t][e], ar[t], bp.x);
                    fma2(acc[t][e], ai[t], bp.y);
                    fma2(acc[t][e], er[t], bp.x);
                    fma2(acc[t][e], ei[t], bp.y);
                }
            }
#pragma unroll
            for (int q = 0; q < 3; q++) {
                const int e  = (q == 0) ? 1 : (q == 1) ? 2 : 5;
                const int et = (q == 0) ? 3 : (q == 1) ? 6 : 7;
                ulonglong2 bpE = wp[e];
                ulonglong2 bpT = wp[et];
#pragma unroll
                for (int t = 0; t < TPT; t++) {
                    fma2(acc[t][e],  ar[t], bpE.x);
                    fma2(acc[t][e],  ai[t], bpE.y);
                    fma2(acc[t][e],  er[t], bpT.x);
                    fma2(acc[t][e],  ei[t], bpT.y);
                    fma2(acc[t][et], ar[t], bpT.x);
                    fma2(acc[t][et], ai[t], bpT.y);
                    fma2(acc[t][et], er[t], bpE.x);
                    fma2(acc[t][et], ei[t], bpE.y);
                }
            }
        }
        const u64 one2 = pk(1.0f, 1.0f);
#pragma unroll
        for (int t = 0; t < TPT; t++) {
            int task = tid + t * H;
            float2 cw = __ldg(gC + task);
            u64 cc = pk(cw.x, cw.y);
            fma2(acc[t][0], one2, cc);
            fma2(acc[t][4], one2, cc);
            fma2(acc[t][8], one2, cc);
#pragma unroll
            for (int e = 0; e < 9; e++) sC[e*T + task] = acc[t][e];
        }
    }
}

template<int S, int NB>
__device__ __forceinline__ void stage_m(const ulonglong2* __restrict__ sWp,
                                        const u64* __restrict__ sC,
                                        u64* __restrict__ sM, int tid)
{
    const int T = U * S;
    if (tid < U * 9) {
        int u = tid / 9, e = tid % 9;
        int i = e / 3, k = e % 3;
        u64 a1 = 0ull, a2 = 0ull, a2c = 0ull;
        const u64* Cu = sC + u * S;
#pragma unroll
        for (int v = 0; v < NB; ++v) {
#pragma unroll
            for (int j = 0; j < 3; ++j) {
                float2 b = up(sWp[v*9 + i*3 + j].x);
                u64 c = Cu[(j*3 + k)*T + v];
                fma2(a1, pk(b.x, b.x), c);
                fma2(a2, pk(b.y, b.y), c);
            }
        }
#pragma unroll
        for (int v = 0; v < NB; ++v) {
#pragma unroll
            for (int j = 0; j < 3; ++j) {
                float2 b = up(sWp[v*9 + j*3 + i].x);
                u64 c = Cu[(j*3 + k)*T + NB + v];
                fma2(a1,  pk(b.x, b.x), c);
                fma2(a2c, pk(b.y, b.y), c);
            }
        }
        float2 p = up(a1), q = up(a2), qc = up(a2c);
        float2 ci = up(Cu[(i*3 + k)*T + 2*NB]);
        sM[u*9 + e] = pk(p.x - q.y + qc.y + ci.x,
                         p.y + q.x - qc.x + ci.y);
    }
}

// ---------------- Fused kernel ----------------

__global__ __launch_bounds__(NT, 5)
void gebl_kernel(const float* __restrict__ x,
                 const float* __restrict__ dw,
                 const float* __restrict__ db,
                 float* __restrict__ out)
{
    __shared__ __align__(16) ulonglong2 sWp[S2 * 9];    // 3600 B (25 channels for layer 2)
    __shared__ u64   sC[9 * T1];                        // 11232 B (layer 1 only)
    __shared__ u64   sM[U * 9];                         // 864 B
    __shared__ __align__(16) ulonglong2 sT[NPAIR];      // 5200 B: {t, ts}
    __shared__ u64   sPart[12 * 13];                    // 1248 B
    __shared__ float sTrRe[U], sTrIm[U], sAbs[U], sScale[U];
    __shared__ float sNormInv;

    const int tid   = threadIdx.x;
    const int point = blockIdx.x;
    const float2* xp = reinterpret_cast<const float2*>(x + (size_t)point * NPTF) + 4 * 9;

    // ---- Build base W1 ----
    if (tid < NB1 * 9) {
        float2 v = __ldg(xp + tid);
        sWp[tid] = make_ulonglong2(pk(v.x, v.y), pk(-v.y, v.x));
    }
    __syncthreads();

    // ---- Layer 1 ----
    stage_c<S1, NB1, 1>(g_A1, g_E1, g_C1, sWp, sC, tid);
    __syncthreads();
    stage_m<S1, NB1>(sWp, sC, sM, tid);
    __syncthreads();

    if (tid < U) {
        const u64* m = sM + tid*9;
        float2 t0 = up(m[0]), t4 = up(m[4]), t8 = up(m[8]);
        float trRe = t0.x + t4.x + t8.x;
        float trIm = t0.y + t4.y + t8.y;
        float t = fmaxf(trRe, 0.0f);
        sAbs[tid]   = t * sqrtf(trRe*trRe + trIm*trIm);
        sScale[tid] = t;
    }
    __syncthreads();
    if (tid == 0) {
        float s = 0.f;
#pragma unroll
        for (int u = 0; u < U; u++) s += sAbs[u];
        sNormInv = 1.0f / fmaxf(s * (1.0f / U), 0.001f);
    }
    __syncthreads();

    // ---- Build ALL 25 W2 channels {b, bs}: 12 scaled, 12 scaled conj-T, identity ----
    for (int idx = tid; idx < S2 * 9; idx += NT) {
        int ch = idx / 9, e = idx % 9;
        int i = e / 3, j = e % 3;
        u64 b, bs;
        if (ch < U) {
            float s = sScale[ch] * sNormInv;
            float2 m = up(sM[ch*9 + e]);
            b  = pk(s*m.x,  s*m.y);
            bs = pk(-s*m.y, s*m.x);
        } else if (ch < 2*U) {
            int k = ch - U;
            float s = sScale[k] * sNormInv;
            float2 m = up(sM[k*9 + j*3 + i]);        // transpose
            float br = s*m.x, bi = -s*m.y;           // conjugate
            b  = pk(br, bi);
            bs = pk(-bi, br);
        } else {
            float d = (i == j) ? 1.0f : 0.0f;
            b  = pk(d, 0.0f);
            bs = pk(0.0f, d);
        }
        sWp[ch*9 + e] = make_ulonglong2(b, bs);
    }
    __syncthreads();

    // ---- t[p] = tr(W2[v] W2[w]) for all 325 symmetric pairs ----
    for (int p = tid; p < NPAIR; p += NT) {
        int v = __ldg(g_pv + p), w = __ldg(g_pw + p);
        const ulonglong2* Wv = sWp + v*9;
        const ulonglong2* Ww = sWp + w*9;
        u64 acc = 0ull;
#pragma unroll
        for (int i = 0; i < 3; i++)
#pragma unroll
            for (int j = 0; j < 3; j++) {
                float2 a = up(Wv[i*3 + j].x);
                ulonglong2 bq = Ww[j*3 + i];
                fma2(acc, pk(a.x, a.x), bq.x);
                fma2(acc, pk(a.y, a.y), bq.y);
            }
        float2 r = up(acc);
        sT[p] = make_ulonglong2(acc, pk(-r.y, r.x));
    }
    __syncthreads();

    // ---- Contraction: tr2[u] = sum_p gtilde[u,p] * t[p]  (12 u x 13 parts) ----
    if (tid < 12 * 13) {
        int u = tid / 13, part = tid % 13;
        const float2* gu = reinterpret_cast<const float2*>(g_T2) + u*NPAIR;
        u64 acc = 0ull;
#pragma unroll
        for (int q = 0; q < 25; q++) {
            int p = part + 13*q;
            float2 g = __ldg(gu + p);
            ulonglong2 tt = sT[p];
            fma2(acc, pk(g.x, g.x), tt.x);
            fma2(acc, pk(g.y, g.y), tt.y);
        }
        sPart[tid] = acc;
    }
    __syncthreads();

    // ---- Layer-2 scalars + head ----
    if (tid < U) {
        float trRe = 0.f, trIm = 0.f;
#pragma unroll
        for (int q = 0; q < 13; q++) {
            float2 f = up(sPart[tid*13 + q]);
            trRe += f.x; trIm += f.y;
        }
        float t = fmaxf(trRe, 0.0f);
        sTrRe[tid]  = trRe;
        sTrIm[tid]  = trIm;
        sAbs[tid]   = t * sqrtf(trRe*trRe + trIm*trIm);
        sScale[tid] = t;
    }
    __syncthreads();
    if (tid == 0) {
        float s = 0.f;
#pragma unroll
        for (int u = 0; u < U; u++) s += sAbs[u];
        float inv_norm = 1.0f / fmaxf(s * (1.0f / U), 0.001f);
        float o = __ldg(&db[0]);
#pragma unroll
        for (int u = 0; u < U; u++) {
            float sc = sScale[u] * inv_norm * (1.0f / 3.0f);
            o = fmaf(sc * sTrRe[u], __ldg(&dw[2*u]),     o);
            o = fmaf(sc * sTrIm[u], __ldg(&dw[2*u + 1]), o);
        }
        out[point] = o;
    }
}

extern "C" void kernel_launch(void* const* d_in, const int* in_sizes, int n_in,
                              void* d_out, int out_size)
{
    const float* x  = (const float*)d_in[0];
    const float* w1 = (const float*)d_in[1];
    const float* w2 = (const float*)d_in[2];
    const float* dw = (const float*)d_in[3];
    const float* db = (const float*)d_in[4];
    float* out = (float*)d_out;

    int points = in_sizes[0] / NPTF;   // 8192

    prep_w<<<(U*NPAIR + 511) / 512, 512>>>(w1, w2);
    gebl_kernel<<<points, NT>>>(x, dw, db, out);
}

// round 15
// speedup vs baseline: 1.8035x; 1.1546x over previous
#include <cuda_runtime.h>
#include <math.h>

// GEBLNet fused kernel, round 15: P/Q-decomposed trace layer 2.
//  t over 625 (v,w) pairs == 144 P=tr(MM) + 144 Q=tr(MM^H) + 12 linear + const,
//  with conj/transpose structure folded into precomputed float4 coeff packs.
//  Layer 1 = round-9 winner verbatim. All layer-2 shared loads coherent.

#define U    12
#define S1   13
#define S2   25
#define NB1  6
#define T1   (U*S1)      // 156
#define NT   160
#define NPTF 180

typedef unsigned long long u64;

__device__ float2 g_A1[NB1*T1], g_C1[T1];
__device__ float4 g_E1[NB1*T1];            // {er, -er, -ei, ei}
__device__ float4 g_cP[U*144];             // coeffs on P[v,w]
__device__ float4 g_cQ[U*144];             // coeffs on Q[v,w]
__device__ float4 g_lin[U*12];             // coeffs on d[v] = tr(Mv~)
__device__ float2 g_cc[U];                 // constant term

__device__ __forceinline__ u64 pk(float lo, float hi) {
    u64 r; asm("mov.b64 %0,{%1,%2};" : "=l"(r) : "f"(lo), "f"(hi)); return r;
}
__device__ __forceinline__ void fma2(u64& d, u64 a, u64 b) {
    asm("fma.rn.f32x2 %0,%1,%2,%0;" : "+l"(d) : "l"(a), "l"(b));
}
__device__ __forceinline__ float2 up(u64 a) {
    float2 f; asm("mov.b64 {%0,%1},%2;" : "=f"(f.x), "=f"(f.y) : "l"(a)); return f;
}

__global__ void prep_w(const float* __restrict__ w1, const float* __restrict__ w2)
{
    int n = blockIdx.x * blockDim.x + threadIdx.x;
    if (n < T1) {
        const float* b = w1 + (size_t)n * S1 * 2;
        for (int w = 0; w < NB1; w++) {
            g_A1[w*T1 + n] = make_float2(b[2*w], b[2*w + 1]);
            float er = b[2*(NB1+w)], ei = b[2*(NB1+w) + 1];
            g_E1[w*T1 + n] = make_float4(er, -er, -ei, ei);
        }
        g_C1[n] = make_float2(b[2*(2*NB1)], b[2*(2*NB1) + 1]);
    }
    if (n < U * 144) {
        int u = n / 144, r = n % 144, v = r / 12, w = r % 12;
        const float* base = w2 + (size_t)u * S2 * S2 * 2;
        // alpha*z + beta*conj(z) -> {c1,c2,c3,c4}: re=c1*zr+c3*zi, im=c2*zr+c4*zi
        // P[v,w]: alpha = g[v][w], beta = g[12+w][12+v]
        {
            float ar = base[(v*S2 + w)*2],            ai = base[(v*S2 + w)*2 + 1];
            float br = base[((12+w)*S2 + 12+v)*2],    bi = base[((12+w)*S2 + 12+v)*2 + 1];
            g_cP[n] = make_float4(ar+br, ai+bi, bi-ai, ar-br);
        }
        // Q[v,w]: alpha = g[v][12+w], beta = g[12+v][w]
        {
            float ar = base[(v*S2 + 12+w)*2],         ai = base[(v*S2 + 12+w)*2 + 1];
            float br = base[((12+v)*S2 + w)*2],       bi = base[((12+v)*S2 + w)*2 + 1];
            g_cQ[n] = make_float4(ar+br, ai+bi, bi-ai, ar-br);
        }
    }
    if (n < U * 12) {
        int u = n / 12, v = n % 12;
        const float* base = w2 + (size_t)u * S2 * S2 * 2;
        // d[v] terms: alpha = g[v][24] + g[24][v], beta = g[12+v][24] + g[24][12+v]
        float ar = base[(v*S2 + 24)*2]        + base[(24*S2 + v)*2];
        float ai = base[(v*S2 + 24)*2 + 1]    + base[(24*S2 + v)*2 + 1];
        float br = base[((12+v)*S2 + 24)*2]   + base[(24*S2 + 12+v)*2];
        float bi = base[((12+v)*S2 + 24)*2+1] + base[(24*S2 + 12+v)*2 + 1];
        g_lin[n] = make_float4(ar+br, ai+bi, bi-ai, ar-br);
    }
    if (n < U) {
        const float* base = w2 + (size_t)n * S2 * S2 * 2;
        g_cc[n] = make_float2(3.0f * base[(24*S2 + 24)*2],
                              3.0f * base[(24*S2 + 24)*2 + 1]);
    }
}

// ---------------- Layer 1 (round-9 winner, verbatim) ----------------

template<int S, int NB, int TPT>
__device__ __forceinline__ void stage_c(const float2* __restrict__ gA,
                                        const float4* __restrict__ gE,
                                        const float2* __restrict__ gC,
                                        const ulonglong2* __restrict__ sWp,
                                        u64* __restrict__ sC, int tid)
{
    const int T = U * S;
    const int H = T / TPT;
    if (tid < H) {
        u64 acc[TPT][9];
#pragma unroll
        for (int t = 0; t < TPT; t++)
#pragma unroll
            for (int e = 0; e < 9; e++) acc[t][e] = 0ull;

#pragma unroll
        for (int w = 0; w < NB; ++w) {
            u64 ar[TPT], ai[TPT], er[TPT], ei[TPT];
#pragma unroll
            for (int t = 0; t < TPT; t++) {
                int task = tid + t * H;
                float2 aw = __ldg(gA + w*T + task);
                float4 ef = __ldg(gE + w*T + task);
                ar[t] = pk(aw.x, aw.x); ai[t] = pk(aw.y, aw.y);
                er[t] = pk(ef.x, ef.y); ei[t] = pk(ef.z, ef.w);
            }
            const ulonglong2* wp = sWp + w*9;
#pragma unroll
            for (int d = 0; d < 3; d++) {
                const int e = d*4;
                ulonglong2 bp = wp[e];
#pragma unroll
                for (int t = 0; t < TPT; t++) {
                    fma2(acc[t][e], ar[t], bp.x);
                    fma2(acc[t][e], ai[t], bp.y);
                    fma2(acc[t][e], er[t], bp.x);
                    fma2(acc[t][e], ei[t], bp.y);
                }
            }
#pragma unroll
            for (int q = 0; q < 3; q++) {
                const int e  = (q == 0) ? 1 : (q == 1) ? 2 : 5;
                const int et = (q == 0) ? 3 : (q == 1) ? 6 : 7;
                ulonglong2 bpE = wp[e];
                ulonglong2 bpT = wp[et];
#pragma unroll
                for (int t = 0; t < TPT; t++) {
                    fma2(acc[t][e],  ar[t], bpE.x);
                    fma2(acc[t][e],  ai[t], bpE.y);
                    fma2(acc[t][e],  er[t], bpT.x);
                    fma2(acc[t][e],  ei[t], bpT.y);
                    fma2(acc[t][et], ar[t], bpT.x);
                    fma2(acc[t][et], ai[t], bpT.y);
                    fma2(acc[t][et], er[t], bpE.x);
                    fma2(acc[t][et], ei[t], bpE.y);
                }
            }
        }
        const u64 one2 = pk(1.0f, 1.0f);
#pragma unroll
        for (int t = 0; t < TPT; t++) {
            int task = tid + t * H;
            float2 cw = __ldg(gC + task);
            u64 cc = pk(cw.x, cw.y);
            fma2(acc[t][0], one2, cc);
            fma2(acc[t][4], one2, cc);
            fma2(acc[t][8], one2, cc);
#pragma unroll
            for (int e = 0; e < 9; e++) sC[e*T + task] = acc[t][e];
        }
    }
}

template<int S, int NB>
__device__ __forceinline__ void stage_m(const ulonglong2* __restrict__ sWp,
                                        const u64* __restrict__ sC,
                                        u64* __restrict__ sM, int tid)
{
    const int T = U * S;
    if (tid < U * 9) {
        int u = tid / 9, e = tid % 9;
        int i = e / 3, k = e % 3;
        u64 a1 = 0ull, a2 = 0ull, a2c = 0ull;
        const u64* Cu = sC + u * S;
#pragma unroll
        for (int v = 0; v < NB; ++v) {
#pragma unroll
            for (int j = 0; j < 3; ++j) {
                float2 b = up(sWp[v*9 + i*3 + j].x);
                u64 c = Cu[(j*3 + k)*T + v];
                fma2(a1, pk(b.x, b.x), c);
                fma2(a2, pk(b.y, b.y), c);
            }
        }
#pragma unroll
        for (int v = 0; v < NB; ++v) {
#pragma unroll
            for (int j = 0; j < 3; ++j) {
                float2 b = up(sWp[v*9 + j*3 + i].x);
                u64 c = Cu[(j*3 + k)*T + NB + v];
                fma2(a1,  pk(b.x, b.x), c);
                fma2(a2c, pk(b.y, b.y), c);
            }
        }
        float2 p = up(a1), q = up(a2), qc = up(a2c);
        float2 ci = up(Cu[(i*3 + k)*T + 2*NB]);
        sM[u*9 + e] = pk(p.x - q.y + qc.y + ci.x,
                         p.y + q.x - qc.x + ci.y);
    }
}

// ---------------- Fused kernel ----------------

__global__ __launch_bounds__(NT, 5)
void gebl_kernel(const float* __restrict__ x,
                 const float* __restrict__ dw,
                 const float* __restrict__ db,
                 float* __restrict__ out)
{
    __shared__ __align__(16) ulonglong2 sWp[NB1 * 9];   // 864 B
    __shared__ u64   sC[9 * T1];                        // 11232 B
    __shared__ u64   sM[U * 9];                         // 864 B (later scaled in place)
    __shared__ __align__(16) ulonglong2 sP2[144];       // {zr,zr},{zi,zi} of P
    __shared__ __align__(16) ulonglong2 sQ2[144];
    __shared__ __align__(16) ulonglong2 sD2[U];
    __shared__ u64   sPart[144];
    __shared__ float sTrRe[U], sTrIm[U], sAbs[U], sScale[U];
    __shared__ float sNormInv;

    const int tid   = threadIdx.x;
    const int point = blockIdx.x;
    const float2* xp = reinterpret_cast<const float2*>(x + (size_t)point * NPTF) + 4 * 9;

    // ---- Build base W1 ----
    if (tid < NB1 * 9) {
        float2 v = __ldg(xp + tid);
        sWp[tid] = make_ulonglong2(pk(v.x, v.y), pk(-v.y, v.x));
    }
    __syncthreads();

    // ---- Layer 1 ----
    stage_c<S1, NB1, 1>(g_A1, g_E1, g_C1, sWp, sC, tid);
    __syncthreads();
    stage_m<S1, NB1>(sWp, sC, sM, tid);
    __syncthreads();

    if (tid < U) {
        const u64* m = sM + tid*9;
        float2 t0 = up(m[0]), t4 = up(m[4]), t8 = up(m[8]);
        float trRe = t0.x + t4.x + t8.x;
        float trIm = t0.y + t4.y + t8.y;
        float t = fmaxf(trRe, 0.0f);
        sAbs[tid]   = t * sqrtf(trRe*trRe + trIm*trIm);
        sScale[tid] = t;
    }
    __syncthreads();
    if (tid == 0) {
        float s = 0.f;
#pragma unroll
        for (int u = 0; u < U; u++) s += sAbs[u];
        sNormInv = 1.0f / fmaxf(s * (1.0f / U), 0.001f);
    }
    __syncthreads();

    // ---- Scale sM in place: Mt[v] = s_v * M[v] ----
    if (tid < U * 9) {
        float s = sScale[tid / 9] * sNormInv;
        float2 m = up(sM[tid]);
        sM[tid] = pk(s * m.x, s * m.y);
    }
    __syncthreads();

    // ---- P[v,w] = tr(Mt_v Mt_w), Q[v,w] = tr(Mt_v Mt_w^H), d[v] = tr(Mt_v) ----
    if (tid < 144) {
        int v = tid / 12, w = tid % 12;
        float2 b[9];
#pragma unroll
        for (int e = 0; e < 9; e++) b[e] = up(sM[w*9 + e]);
        float Pr = 0.f, Pi = 0.f, Qr = 0.f, Qi = 0.f;
#pragma unroll
        for (int i = 0; i < 3; i++)
#pragma unroll
            for (int j = 0; j < 3; j++) {
                float2 a  = up(sM[v*9 + i*3 + j]);   // broadcast within 12-lane group
                float2 bt = b[j*3 + i];
                float2 bd = b[i*3 + j];
                Pr = fmaf(a.x, bt.x, Pr); Pr = fmaf(-a.y, bt.y, Pr);
                Pi = fmaf(a.x, bt.y, Pi); Pi = fmaf( a.y, bt.x, Pi);
                Qr = fmaf(a.x, bd.x, Qr); Qr = fmaf( a.y, bd.y, Qr);
                Qi = fmaf(a.y, bd.x, Qi); Qi = fmaf(-a.x, bd.y, Qi);
            }
        sP2[tid] = make_ulonglong2(pk(Pr, Pr), pk(Pi, Pi));
        sQ2[tid] = make_ulonglong2(pk(Qr, Qr), pk(Qi, Qi));
        if (v == w) {
            float dr = b[0].x + b[4].x + b[8].x;
            float di = b[0].y + b[4].y + b[8].y;
            sD2[v] = make_ulonglong2(pk(dr, dr), pk(di, di));
        }
    }
    __syncthreads();

    // ---- Contraction: partials over v for each (u, pw) ----
    if (tid < 144) {
        int u = tid / 12, pw = tid % 12;
        u64 acc = 0ull;
        const float4* cp = g_cP + u*144 + pw;
        const float4* cq = g_cQ + u*144 + pw;
#pragma unroll
        for (int v = 0; v < 12; v++) {
            float4 c1 = __ldg(cp + v*12);
            ulonglong2 zp = sP2[v*12 + pw];
            fma2(acc, pk(c1.x, c1.y), zp.x);
            fma2(acc, pk(c1.z, c1.w), zp.y);
            float4 c2 = __ldg(cq + v*12);
            ulonglong2 zq = sQ2[v*12 + pw];
            fma2(acc, pk(c2.x, c2.y), zq.x);
            fma2(acc, pk(c2.z, c2.w), zq.y);
        }
        sPart[tid] = acc;
    }
    __syncthreads();

    // ---- Per-u reduce + linear + const -> layer-2 scalars ----
    if (tid < U) {
        const u64 one2 = pk(1.0f, 1.0f);
        u64 acc = 0ull;
#pragma unroll
        for (int pw = 0; pw < 12; pw++) fma2(acc, one2, sPart[tid*12 + pw]);
#pragma unroll
        for (int v = 0; v < 12; v++) {
            float4 lv = __ldg(g_lin + tid*12 + v);
            ulonglong2 d = sD2[v];
            fma2(acc, pk(lv.x, lv.y), d.x);
            fma2(acc, pk(lv.z, lv.w), d.y);
        }
        float2 cc = __ldg(g_cc + tid);
        fma2(acc, one2, pk(cc.x, cc.y));
        float2 tr = up(acc);
        float t = fmaxf(tr.x, 0.0f);
        sTrRe[tid]  = tr.x;
        sTrIm[tid]  = tr.y;
        sAbs[tid]   = t * sqrtf(tr.x*tr.x + tr.y*tr.y);
        sScale[tid] = t;
    }
    __syncthreads();
    if (tid == 0) {
        float s = 0.f;
#pragma unroll
        for (int u = 0; u < U; u++) s += sAbs[u];
        float inv_norm = 1.0f / fmaxf(s * (1.0f / U), 0.001f);
        float o = __ldg(&db[0]);
#pragma unroll
        for (int u = 0; u < U; u++) {
            float sc = sScale[u] * inv_norm * (1.0f / 3.0f);
            o = fmaf(sc * sTrRe[u], __ldg(&dw[2*u]),     o);
            o = fmaf(sc * sTrIm[u], __ldg(&dw[2*u + 1]), o);
        }
        out[point] = o;
    }
}

extern "C" void kernel_launch(void* const* d_in, const int* in_sizes, int n_in,
                              void* d_out, int out_size)
{
    const float* x  = (const float*)d_in[0];
    const float* w1 = (const float*)d_in[1];
    const float* w2 = (const float*)d_in[2];
    const float* dw = (const float*)d_in[3];
    const float* db = (const float*)d_in[4];
    float* out = (float*)d_out;

    int points = in_sizes[0] / NPTF;   // 8192

    prep_w<<<4, 512>>>(w1, w2);
    gebl_kernel<<<points, NT>>>(x, dw, db, out);
}

// round 16
// speedup vs baseline: 1.8073x; 1.0021x over previous
#include <cuda_runtime.h>
#include <math.h>

// GEBLNet fused kernel, round 16 = round-15 winner + two changes:
//  (1) layer-1 stage_c TPT=2 (halves broadcast-LDS wavefronts; justified now
//      that L1 is at 88% = throughput wall, not latency)
//  (2) sM padded to stride 10 u64 (16B aligned) -> trace stage loads a[]/b[]
//      as vectorized LDS.128 (18 scalar loads -> 10 vector loads per thread)

#define U    12
#define S1   13
#define S2   25
#define NB1  6
#define T1   (U*S1)      // 156
#define NT   160
#define NPTF 180
#define MST  10          // padded u64 stride of sM per channel

typedef unsigned long long u64;

__device__ float2 g_A1[NB1*T1], g_C1[T1];
__device__ float4 g_E1[NB1*T1];            // {er, -er, -ei, ei}
__device__ float4 g_cP[U*144];             // coeffs on P[v,w]
__device__ float4 g_cQ[U*144];             // coeffs on Q[v,w]
__device__ float4 g_lin[U*12];             // coeffs on d[v] = tr(Mv~)
__device__ float2 g_cc[U];                 // constant term

__device__ __forceinline__ u64 pk(float lo, float hi) {
    u64 r; asm("mov.b64 %0,{%1,%2};" : "=l"(r) : "f"(lo), "f"(hi)); return r;
}
__device__ __forceinline__ void fma2(u64& d, u64 a, u64 b) {
    asm("fma.rn.f32x2 %0,%1,%2,%0;" : "+l"(d) : "l"(a), "l"(b));
}
__device__ __forceinline__ float2 up(u64 a) {
    float2 f; asm("mov.b64 {%0,%1},%2;" : "=f"(f.x), "=f"(f.y) : "l"(a)); return f;
}

__global__ void prep_w(const float* __restrict__ w1, const float* __restrict__ w2)
{
    int n = blockIdx.x * blockDim.x + threadIdx.x;
    if (n < T1) {
        const float* b = w1 + (size_t)n * S1 * 2;
        for (int w = 0; w < NB1; w++) {
            g_A1[w*T1 + n] = make_float2(b[2*w], b[2*w + 1]);
            float er = b[2*(NB1+w)], ei = b[2*(NB1+w) + 1];
            g_E1[w*T1 + n] = make_float4(er, -er, -ei, ei);
        }
        g_C1[n] = make_float2(b[2*(2*NB1)], b[2*(2*NB1) + 1]);
    }
    if (n < U * 144) {
        int u = n / 144, r = n % 144, v = r / 12, w = r % 12;
        const float* base = w2 + (size_t)u * S2 * S2 * 2;
        // alpha*z + beta*conj(z) -> {c1,c2,c3,c4}: re=c1*zr+c3*zi, im=c2*zr+c4*zi
        // P[v,w]: alpha = g[v][w], beta = g[12+w][12+v]
        {
            float ar = base[(v*S2 + w)*2],            ai = base[(v*S2 + w)*2 + 1];
            float br = base[((12+w)*S2 + 12+v)*2],    bi = base[((12+w)*S2 + 12+v)*2 + 1];
            g_cP[n] = make_float4(ar+br, ai+bi, bi-ai, ar-br);
        }
        // Q[v,w]: alpha = g[v][12+w], beta = g[12+v][w]
        {
            float ar = base[(v*S2 + 12+w)*2],         ai = base[(v*S2 + 12+w)*2 + 1];
            float br = base[((12+v)*S2 + w)*2],       bi = base[((12+v)*S2 + w)*2 + 1];
            g_cQ[n] = make_float4(ar+br, ai+bi, bi-ai, ar-br);
        }
    }
    if (n < U * 12) {
        int u = n / 12, v = n % 12;
        const float* base = w2 + (size_t)u * S2 * S2 * 2;
        float ar = base[(v*S2 + 24)*2]        + base[(24*S2 + v)*2];
        float ai = base[(v*S2 + 24)*2 + 1]    + base[(24*S2 + v)*2 + 1];
        float br = base[((12+v)*S2 + 24)*2]   + base[(24*S2 + 12+v)*2];
        float bi = base[((12+v)*S2 + 24)*2+1] + base[(24*S2 + 12+v)*2 + 1];
        g_lin[n] = make_float4(ar+br, ai+bi, bi-ai, ar-br);
    }
    if (n < U) {
        const float* base = w2 + (size_t)n * S2 * S2 * 2;
        g_cc[n] = make_float2(3.0f * base[(24*S2 + 24)*2],
                              3.0f * base[(24*S2 + 24)*2 + 1]);
    }
}

// ---------------- Layer 1 (round-9 core) ----------------

template<int S, int NB, int TPT>
__device__ __forceinline__ void stage_c(const float2* __restrict__ gA,
                                        const float4* __restrict__ gE,
                                        const float2* __restrict__ gC,
                                        const ulonglong2* __restrict__ sWp,
                                        u64* __restrict__ sC, int tid)
{
    const int T = U * S;
    const int H = T / TPT;
    if (tid < H) {
        u64 acc[TPT][9];
#pragma unroll
        for (int t = 0; t < TPT; t++)
#pragma unroll
            for (int e = 0; e < 9; e++) acc[t][e] = 0ull;

#pragma unroll
        for (int w = 0; w < NB; ++w) {
            u64 ar[TPT], ai[TPT], er[TPT], ei[TPT];
#pragma unroll
            for (int t = 0; t < TPT; t++) {
                int task = tid + t * H;
                float2 aw = __ldg(gA + w*T + task);
                float4 ef = __ldg(gE + w*T + task);
                ar[t] = pk(aw.x, aw.x); ai[t] = pk(aw.y, aw.y);
                er[t] = pk(ef.x, ef.y); ei[t] = pk(ef.z, ef.w);
            }
            const ulonglong2* wp = sWp + w*9;
#pragma unroll
            for (int d = 0; d < 3; d++) {
                const int e = d*4;
                ulonglong2 bp = wp[e];
#pragma unroll
                for (int t = 0; t < TPT; t++) {
                    fma2(acc[t][e], ar[t], bp.x);
                    fma2(acc[t][e], ai[t], bp.y);
                    fma2(acc[t][e], er[t], bp.x);
                    fma2(acc[t][e], ei[t], bp.y);
                }
            }
#pragma unroll
            for (int q = 0; q < 3; q++) {
                const int e  = (q == 0) ? 1 : (q == 1) ? 2 : 5;
                const int et = (q == 0) ? 3 : (q == 1) ? 6 : 7;
                ulonglong2 bpE = wp[e];
                ulonglong2 bpT = wp[et];
#pragma unroll
                for (int t = 0; t < TPT; t++) {
                    fma2(acc[t][e],  ar[t], bpE.x);
                    fma2(acc[t][e],  ai[t], bpE.y);
                    fma2(acc[t][e],  er[t], bpT.x);
                    fma2(acc[t][e],  ei[t], bpT.y);
                    fma2(acc[t][et], ar[t], bpT.x);
                    fma2(acc[t][et], ai[t], bpT.y);
                    fma2(acc[t][et], er[t], bpE.x);
                    fma2(acc[t][et], ei[t], bpE.y);
                }
            }
        }
        const u64 one2 = pk(1.0f, 1.0f);
#pragma unroll
        for (int t = 0; t < TPT; t++) {
            int task = tid + t * H;
            float2 cw = __ldg(gC + task);
            u64 cc = pk(cw.x, cw.y);
            fma2(acc[t][0], one2, cc);
            fma2(acc[t][4], one2, cc);
            fma2(acc[t][8], one2, cc);
#pragma unroll
            for (int e = 0; e < 9; e++) sC[e*T + task] = acc[t][e];
        }
    }
}

// stage_m writes into the PADDED sM (stride MST)
template<int S, int NB>
__device__ __forceinline__ void stage_m(const ulonglong2* __restrict__ sWp,
                                        const u64* __restrict__ sC,
                                        u64* __restrict__ sM, int tid)
{
    const int T = U * S;
    if (tid < U * 9) {
        int u = tid / 9, e = tid % 9;
        int i = e / 3, k = e % 3;
        u64 a1 = 0ull, a2 = 0ull, a2c = 0ull;
        const u64* Cu = sC + u * S;
#pragma unroll
        for (int v = 0; v < NB; ++v) {
#pragma unroll
            for (int j = 0; j < 3; ++j) {
                float2 b = up(sWp[v*9 + i*3 + j].x);
                u64 c = Cu[(j*3 + k)*T + v];
                fma2(a1, pk(b.x, b.x), c);
                fma2(a2, pk(b.y, b.y), c);
            }
        }
#pragma unroll
        for (int v = 0; v < NB; ++v) {
#pragma unroll
            for (int j = 0; j < 3; ++j) {
                float2 b = up(sWp[v*9 + j*3 + i].x);
                u64 c = Cu[(j*3 + k)*T + NB + v];
                fma2(a1,  pk(b.x, b.x), c);
                fma2(a2c, pk(b.y, b.y), c);
            }
        }
        float2 p = up(a1), q = up(a2), qc = up(a2c);
        float2 ci = up(Cu[(i*3 + k)*T + 2*NB]);
        sM[u*MST + e] = pk(p.x - q.y + qc.y + ci.x,
                           p.y + q.x - qc.x + ci.y);
    }
}

// ---------------- Fused kernel ----------------

__global__ __launch_bounds__(NT, 5)
void gebl_kernel(const float* __restrict__ x,
                 const float* __restrict__ dw,
                 const float* __restrict__ db,
                 float* __restrict__ out)
{
    __shared__ __align__(16) ulonglong2 sWp[NB1 * 9];   // 864 B
    __shared__ u64   sC[9 * T1];                        // 11232 B
    __shared__ __align__(16) u64 sM[U * MST];           // 960 B (padded stride 10)
    __shared__ __align__(16) ulonglong2 sP2[144];       // {zr,zr},{zi,zi} of P
    __shared__ __align__(16) ulonglong2 sQ2[144];
    __shared__ __align__(16) ulonglong2 sD2[U];
    __shared__ u64   sPart[144];
    __shared__ float sTrRe[U], sTrIm[U], sAbs[U], sScale[U];
    __shared__ float sNormInv;

    const int tid   = threadIdx.x;
    const int point = blockIdx.x;
    const float2* xp = reinterpret_cast<const float2*>(x + (size_t)point * NPTF) + 4 * 9;

    // ---- Build base W1 ----
    if (tid < NB1 * 9) {
        float2 v = __ldg(xp + tid);
        sWp[tid] = make_ulonglong2(pk(v.x, v.y), pk(-v.y, v.x));
    }
    __syncthreads();

    // ---- Layer 1 (TPT=2) ----
    stage_c<S1, NB1, 2>(g_A1, g_E1, g_C1, sWp, sC, tid);
    __syncthreads();
    stage_m<S1, NB1>(sWp, sC, sM, tid);
    __syncthreads();

    if (tid < U) {
        const u64* m = sM + tid*MST;
        float2 t0 = up(m[0]), t4 = up(m[4]), t8 = up(m[8]);
        float trRe = t0.x + t4.x + t8.x;
        float trIm = t0.y + t4.y + t8.y;
        float t = fmaxf(trRe, 0.0f);
        sAbs[tid]   = t * sqrtf(trRe*trRe + trIm*trIm);
        sScale[tid] = t;
    }
    __syncthreads();
    if (tid == 0) {
        float s = 0.f;
#pragma unroll
        for (int u = 0; u < U; u++) s += sAbs[u];
        sNormInv = 1.0f / fmaxf(s * (1.0f / U), 0.001f);
    }
    __syncthreads();

    // ---- Scale sM in place: Mt[v] = s_v * M[v] ----
    if (tid < U * 9) {
        int u = tid / 9, e = tid % 9;
        float s = sScale[u] * sNormInv;
        float2 m = up(sM[u*MST + e]);
        sM[u*MST + e] = pk(s * m.x, s * m.y);
    }
    __syncthreads();

    // ---- P[v,w] = tr(Mt_v Mt_w), Q[v,w] = tr(Mt_v Mt_w^H), d[v] = tr(Mt_v) ----
    if (tid < 144) {
        int v = tid / 12, w = tid % 12;
        // vectorized loads (sM stride 10 u64 = 80 B, 16B aligned)
        const ulonglong2* bv = reinterpret_cast<const ulonglong2*>(sM + w*MST);
        const ulonglong2* av = reinterpret_cast<const ulonglong2*>(sM + v*MST);
        float2 b[9], a[9];
#pragma unroll
        for (int m2 = 0; m2 < 4; m2++) {
            ulonglong2 bb = bv[m2];
            b[2*m2]   = up(bb.x); b[2*m2+1] = up(bb.y);
            ulonglong2 aa = av[m2];
            a[2*m2]   = up(aa.x); a[2*m2+1] = up(aa.y);
        }
        b[8] = up(sM[w*MST + 8]);
        a[8] = up(sM[v*MST + 8]);

        float Pr = 0.f, Pi = 0.f, Qr = 0.f, Qi = 0.f;
#pragma unroll
        for (int i = 0; i < 3; i++)
#pragma unroll
            for (int j = 0; j < 3; j++) {
                float2 av2 = a[i*3 + j];
                float2 bt  = b[j*3 + i];
                float2 bd  = b[i*3 + j];
                Pr = fmaf(av2.x, bt.x, Pr); Pr = fmaf(-av2.y, bt.y, Pr);
                Pi = fmaf(av2.x, bt.y, Pi); Pi = fmaf( av2.y, bt.x, Pi);
                Qr = fmaf(av2.x, bd.x, Qr); Qr = fmaf( av2.y, bd.y, Qr);
                Qi = fmaf(av2.y, bd.x, Qi); Qi = fmaf(-av2.x, bd.y, Qi);
            }
        sP2[tid] = make_ulonglong2(pk(Pr, Pr), pk(Pi, Pi));
        sQ2[tid] = make_ulonglong2(pk(Qr, Qr), pk(Qi, Qi));
        if (v == w) {
            float dr = b[0].x + b[4].x + b[8].x;
            float di = b[0].y + b[4].y + b[8].y;
            sD2[v] = make_ulonglong2(pk(dr, dr), pk(di, di));
        }
    }
    __syncthreads();

    // ---- Contraction: partials over v for each (u, pw) ----
    if (tid < 144) {
        int u = tid / 12, pw = tid % 12;
        u64 acc = 0ull;
        const float4* cp = g_cP + u*144 + pw;
        const float4* cq = g_cQ + u*144 + pw;
#pragma unroll
        for (int v = 0; v < 12; v++) {
            float4 c1 = __ldg(cp + v*12);
            ulonglong2 zp = sP2[v*12 + pw];
            fma2(acc, pk(c1.x, c1.y), zp.x);
            fma2(acc, pk(c1.z, c1.w), zp.y);
            float4 c2 = __ldg(cq + v*12);
            ulonglong2 zq = sQ2[v*12 + pw];
            fma2(acc, pk(c2.x, c2.y), zq.x);
            fma2(acc, pk(c2.z, c2.w), zq.y);
        }
        sPart[tid] = acc;
    }
    __syncthreads();

    // ---- Per-u reduce + linear + const -> layer-2 scalars ----
    if (tid < U) {
        const u64 one2 = pk(1.0f, 1.0f);
        u64 acc = 0ull;
#pragma unroll
        for (int pw = 0; pw < 12; pw++) fma2(acc, one2, sPart[tid*12 + pw]);
#pragma unroll
        for (int v = 0; v < 12; v++) {
            float4 lv = __ldg(g_lin + tid*12 + v);
            ulonglong2 d = sD2[v];
            fma2(acc, pk(lv.x, lv.y), d.x);
            fma2(acc, pk(lv.z, lv.w), d.y);
        }
        float2 cc = __ldg(g_cc + tid);
        fma2(acc, one2, pk(cc.x, cc.y));
        float2 tr = up(acc);
        float t = fmaxf(tr.x, 0.0f);
        sTrRe[tid]  = tr.x;
        sTrIm[tid]  = tr.y;
        sAbs[tid]   = t * sqrtf(tr.x*tr.x + tr.y*tr.y);
        sScale[tid] = t;
    }
    __syncthreads();
    if (tid == 0) {
        float s = 0.f;
#pragma unroll
        for (int u = 0; u < U; u++) s += sAbs[u];
        float inv_norm = 1.0f / fmaxf(s * (1.0f / U), 0.001f);
        float o = __ldg(&db[0]);
#pragma unroll
        for (int u = 0; u < U; u++) {
            float sc = sScale[u] * inv_norm * (1.0f / 3.0f);
            o = fmaf(sc * sTrRe[u], __ldg(&dw[2*u]),     o);
            o = fmaf(sc * sTrIm[u], __ldg(&dw[2*u + 1]), o);
        }
        out[point] = o;
    }
}

extern "C" void kernel_launch(void* const* d_in, const int* in_sizes, int n_in,
                              void* d_out, int out_size)
{
    const float* x  = (const float*)d_in[0];
    const float* w1 = (const float*)d_in[1];
    const float* w2 = (const float*)d_in[2];
    const float* dw = (const float*)d_in[3];
    const float* db = (const float*)d_in[4];
    float* out = (float*)d_out;

    int points = in_sizes[0] / NPTF;   // 8192

    prep_w<<<4, 512>>>(w1, w2);
    gebl_kernel<<<points, NT>>>(x, dw, db, out);
}

// round 17
// speedup vs baseline: 1.9884x; 1.1002x over previous
#include <cuda_runtime.h>
#include <math.h>

// GEBLNet fused kernel, round 17 = round-16 + layer-2 tail trims:
//  (1) P/Q/D stored as u64; contraction in scalar FFMA (half LDS wf, no packs)
//  (2) M-scaling folded into trace stage (s_v*s_w on P/Q, s_v on d)
//  (3) shuffle-fused reductions (3 fewer barriers)

#define U    12
#define S1   13
#define S2   25
#define NB1  6
#define T1   (U*S1)      // 156
#define NT   160
#define NPTF 180
#define MST  10          // padded u64 stride of sM per channel

typedef unsigned long long u64;

__device__ float2 g_A1[NB1*T1], g_C1[T1];
__device__ float4 g_E1[NB1*T1];            // {er, -er, -ei, ei}
__device__ float4 g_cP[U*144];             // coeffs on P[v,w]
__device__ float4 g_cQ[U*144];             // coeffs on Q[v,w]
__device__ float4 g_lin[U*12];             // coeffs on d[v]
__device__ float2 g_cc[U];                 // constant term

__device__ __forceinline__ u64 pk(float lo, float hi) {
    u64 r; asm("mov.b64 %0,{%1,%2};" : "=l"(r) : "f"(lo), "f"(hi)); return r;
}
__device__ __forceinline__ void fma2(u64& d, u64 a, u64 b) {
    asm("fma.rn.f32x2 %0,%1,%2,%0;" : "+l"(d) : "l"(a), "l"(b));
}
__device__ __forceinline__ float2 up(u64 a) {
    float2 f; asm("mov.b64 {%0,%1},%2;" : "=f"(f.x), "=f"(f.y) : "l"(a)); return f;
}

__global__ void prep_w(const float* __restrict__ w1, const float* __restrict__ w2)
{
    int n = blockIdx.x * blockDim.x + threadIdx.x;
    if (n < T1) {
        const float* b = w1 + (size_t)n * S1 * 2;
        for (int w = 0; w < NB1; w++) {
            g_A1[w*T1 + n] = make_float2(b[2*w], b[2*w + 1]);
            float er = b[2*(NB1+w)], ei = b[2*(NB1+w) + 1];
            g_E1[w*T1 + n] = make_float4(er, -er, -ei, ei);
        }
        g_C1[n] = make_float2(b[2*(2*NB1)], b[2*(2*NB1) + 1]);
    }
    if (n < U * 144) {
        int u = n / 144, r = n % 144, v = r / 12, w = r % 12;
        const float* base = w2 + (size_t)u * S2 * S2 * 2;
        // alpha*z + beta*conj(z) -> {c1,c2,c3,c4}: re=c1*zr+c3*zi, im=c2*zr+c4*zi
        {
            float ar = base[(v*S2 + w)*2],            ai = base[(v*S2 + w)*2 + 1];
            float br = base[((12+w)*S2 + 12+v)*2],    bi = base[((12+w)*S2 + 12+v)*2 + 1];
            g_cP[n] = make_float4(ar+br, ai+bi, bi-ai, ar-br);
        }
        {
            float ar = base[(v*S2 + 12+w)*2],         ai = base[(v*S2 + 12+w)*2 + 1];
            float br = base[((12+v)*S2 + w)*2],       bi = base[((12+v)*S2 + w)*2 + 1];
            g_cQ[n] = make_float4(ar+br, ai+bi, bi-ai, ar-br);
        }
    }
    if (n < U * 12) {
        int u = n / 12, v = n % 12;
        const float* base = w2 + (size_t)u * S2 * S2 * 2;
        float ar = base[(v*S2 + 24)*2]        + base[(24*S2 + v)*2];
        float ai = base[(v*S2 + 24)*2 + 1]    + base[(24*S2 + v)*2 + 1];
        float br = base[((12+v)*S2 + 24)*2]   + base[(24*S2 + 12+v)*2];
        float bi = base[((12+v)*S2 + 24)*2+1] + base[(24*S2 + 12+v)*2 + 1];
        g_lin[n] = make_float4(ar+br, ai+bi, bi-ai, ar-br);
    }
    if (n < U) {
        const float* base = w2 + (size_t)n * S2 * S2 * 2;
        g_cc[n] = make_float2(3.0f * base[(24*S2 + 24)*2],
                              3.0f * base[(24*S2 + 24)*2 + 1]);
    }
}

// ---------------- Layer 1 (round-9 core, TPT template) ----------------

template<int S, int NB, int TPT>
__device__ __forceinline__ void stage_c(const float2* __restrict__ gA,
                                        const float4* __restrict__ gE,
                                        const float2* __restrict__ gC,
                                        const ulonglong2* __restrict__ sWp,
                                        u64* __restrict__ sC, int tid)
{
    const int T = U * S;
    const int H = T / TPT;
    if (tid < H) {
        u64 acc[TPT][9];
#pragma unroll
        for (int t = 0; t < TPT; t++)
#pragma unroll
            for (int e = 0; e < 9; e++) acc[t][e] = 0ull;

#pragma unroll
        for (int w = 0; w < NB; ++w) {
            u64 ar[TPT], ai[TPT], er[TPT], ei[TPT];
#pragma unroll
            for (int t = 0; t < TPT; t++) {
                int task = tid + t * H;
                float2 aw = __ldg(gA + w*T + task);
                float4 ef = __ldg(gE + w*T + task);
                ar[t] = pk(aw.x, aw.x); ai[t] = pk(aw.y, aw.y);
                er[t] = pk(ef.x, ef.y); ei[t] = pk(ef.z, ef.w);
            }
            const ulonglong2* wp = sWp + w*9;
#pragma unroll
            for (int d = 0; d < 3; d++) {
                const int e = d*4;
                ulonglong2 bp = wp[e];
#pragma unroll
                for (int t = 0; t < TPT; t++) {
                    fma2(acc[t][e], ar[t], bp.x);
                    fma2(acc[t][e], ai[t], bp.y);
                    fma2(acc[t][e], er[t], bp.x);
                    fma2(acc[t][e], ei[t], bp.y);
                }
            }
#pragma unroll
            for (int q = 0; q < 3; q++) {
                const int e  = (q == 0) ? 1 : (q == 1) ? 2 : 5;
                const int et = (q == 0) ? 3 : (q == 1) ? 6 : 7;
                ulonglong2 bpE = wp[e];
                ulonglong2 bpT = wp[et];
#pragma unroll
                for (int t = 0; t < TPT; t++) {
                    fma2(acc[t][e],  ar[t], bpE.x);
                    fma2(acc[t][e],  ai[t], bpE.y);
                    fma2(acc[t][e],  er[t], bpT.x);
                    fma2(acc[t][e],  ei[t], bpT.y);
                    fma2(acc[t][et], ar[t], bpT.x);
                    fma2(acc[t][et], ai[t], bpT.y);
                    fma2(acc[t][et], er[t], bpE.x);
                    fma2(acc[t][et], ei[t], bpE.y);
                }
            }
        }
        const u64 one2 = pk(1.0f, 1.0f);
#pragma unroll
        for (int t = 0; t < TPT; t++) {
            int task = tid + t * H;
            float2 cw = __ldg(gC + task);
            u64 cc = pk(cw.x, cw.y);
            fma2(acc[t][0], one2, cc);
            fma2(acc[t][4], one2, cc);
            fma2(acc[t][8], one2, cc);
#pragma unroll
            for (int e = 0; e < 9; e++) sC[e*T + task] = acc[t][e];
        }
    }
}

// stage_m writes into the PADDED sM (stride MST)
template<int S, int NB>
__device__ __forceinline__ void stage_m(const ulonglong2* __restrict__ sWp,
                                        const u64* __restrict__ sC,
                                        u64* __restrict__ sM, int tid)
{
    const int T = U * S;
    if (tid < U * 9) {
        int u = tid / 9, e = tid % 9;
        int i = e / 3, k = e % 3;
        u64 a1 = 0ull, a2 = 0ull, a2c = 0ull;
        const u64* Cu = sC + u * S;
#pragma unroll
        for (int v = 0; v < NB; ++v) {
#pragma unroll
            for (int j = 0; j < 3; ++j) {
                float2 b = up(sWp[v*9 + i*3 + j].x);
                u64 c = Cu[(j*3 + k)*T + v];
                fma2(a1, pk(b.x, b.x), c);
                fma2(a2, pk(b.y, b.y), c);
            }
        }
#pragma unroll
        for (int v = 0; v < NB; ++v) {
#pragma unroll
            for (int j = 0; j < 3; ++j) {
                float2 b = up(sWp[v*9 + j*3 + i].x);
                u64 c = Cu[(j*3 + k)*T + NB + v];
                fma2(a1,  pk(b.x, b.x), c);
                fma2(a2c, pk(b.y, b.y), c);
            }
        }
        float2 p = up(a1), q = up(a2), qc = up(a2c);
        float2 ci = up(Cu[(i*3 + k)*T + 2*NB]);
        sM[u*MST + e] = pk(p.x - q.y + qc.y + ci.x,
                           p.y + q.x - qc.x + ci.y);
    }
}

// ---------------- Fused kernel ----------------

__global__ __launch_bounds__(NT, 5)
void gebl_kernel(const float* __restrict__ x,
                 const float* __restrict__ dw,
                 const float* __restrict__ db,
                 float* __restrict__ out)
{
    __shared__ __align__(16) ulonglong2 sWp[NB1 * 9];   // 864 B
    __shared__ u64   sC[9 * T1];                        // 11232 B
    __shared__ __align__(16) u64 sM[U * MST];           // 960 B (padded stride 10)
    __shared__ __align__(16) u64 sP[144], sQ[144];      // plain {re,im}
    __shared__ u64   sD[U];
    __shared__ float2 sPart[144];
    __shared__ float sSc[U];                            // relu(tr)*invnorm

    const int tid   = threadIdx.x;
    const int point = blockIdx.x;
    const float2* xp = reinterpret_cast<const float2*>(x + (size_t)point * NPTF) + 4 * 9;

    // ---- Build base W1 ----
    if (tid < NB1 * 9) {
        float2 v = __ldg(xp + tid);
        sWp[tid] = make_ulonglong2(pk(v.x, v.y), pk(-v.y, v.x));
    }
    __syncthreads();

    // ---- Layer 1 ----
    stage_c<S1, NB1, 2>(g_A1, g_E1, g_C1, sWp, sC, tid);
    __syncthreads();
    stage_m<S1, NB1>(sWp, sC, sM, tid);
    __syncthreads();

    // ---- Fused layer-1 reduce (warp 0, shuffle) -> sSc ----
    if (tid < 32) {
        float t = 0.f, ab = 0.f;
        if (tid < U) {
            const u64* m = sM + tid*MST;
            float2 t0 = up(m[0]), t4 = up(m[4]), t8 = up(m[8]);
            float trRe = t0.x + t4.x + t8.x;
            float trIm = t0.y + t4.y + t8.y;
            t  = fmaxf(trRe, 0.0f);
            ab = t * sqrtf(trRe*trRe + trIm*trIm);
        }
        float s = ab;
#pragma unroll
        for (int off = 8; off >= 1; off >>= 1)
            s += __shfl_xor_sync(0xffffffffu, s, off, 16);
        float invn = 1.0f / fmaxf(s * (1.0f / U), 0.001f);
        if (tid < U) sSc[tid] = t * invn;
    }
    __syncthreads();

    // ---- Trace stage: P,Q,d of UNscaled M; scales folded at the end ----
    if (tid < 144) {
        int v = tid / 12, w = tid % 12;
        const ulonglong2* bv = reinterpret_cast<const ulonglong2*>(sM + w*MST);
        const ulonglong2* av = reinterpret_cast<const ulonglong2*>(sM + v*MST);
        float2 b[9], a[9];
#pragma unroll
        for (int m2 = 0; m2 < 4; m2++) {
            ulonglong2 bb = bv[m2];
            b[2*m2]   = up(bb.x); b[2*m2+1] = up(bb.y);
            ulonglong2 aa = av[m2];
            a[2*m2]   = up(aa.x); a[2*m2+1] = up(aa.y);
        }
        b[8] = up(sM[w*MST + 8]);
        a[8] = up(sM[v*MST + 8]);

        float Pr = 0.f, Pi = 0.f, Qr = 0.f, Qi = 0.f;
#pragma unroll
        for (int i = 0; i < 3; i++)
#pragma unroll
            for (int j = 0; j < 3; j++) {
                float2 av2 = a[i*3 + j];
                float2 bt  = b[j*3 + i];
                float2 bd  = b[i*3 + j];
                Pr = fmaf(av2.x, bt.x, Pr); Pr = fmaf(-av2.y, bt.y, Pr);
                Pi = fmaf(av2.x, bt.y, Pi); Pi = fmaf( av2.y, bt.x, Pi);
                Qr = fmaf(av2.x, bd.x, Qr); Qr = fmaf( av2.y, bd.y, Qr);
                Qi = fmaf(av2.y, bd.x, Qi); Qi = fmaf(-av2.x, bd.y, Qi);
            }
        float sv = sSc[v], sw = sSc[w];
        float svw = sv * sw;
        sP[tid] = pk(Pr * svw, Pi * svw);
        sQ[tid] = pk(Qr * svw, Qi * svw);
        if (v == w) {
            float dr = b[0].x + b[4].x + b[8].x;
            float di = b[0].y + b[4].y + b[8].y;
            sD[v] = pk(dr * sv, di * sv);
        }
    }
    __syncthreads();

    // ---- Contraction (scalar FFMA): partials over v for each (u, pw) ----
    if (tid < 144) {
        int u = tid / 12, pw = tid % 12;
        float accR = 0.f, accI = 0.f;
        const float4* cp = g_cP + u*144 + pw;
        const float4* cq = g_cQ + u*144 + pw;
#pragma unroll
        for (int v = 0; v < 12; v++) {
            float4 c1 = __ldg(cp + v*12);
            float2 zp = up(sP[v*12 + pw]);
            accR = fmaf(c1.x, zp.x, accR); accR = fmaf(c1.z, zp.y, accR);
            accI = fmaf(c1.y, zp.x, accI); accI = fmaf(c1.w, zp.y, accI);
            float4 c2 = __ldg(cq + v*12);
            float2 zq = up(sQ[v*12 + pw]);
            accR = fmaf(c2.x, zq.x, accR); accR = fmaf(c2.z, zq.y, accR);
            accI = fmaf(c2.y, zq.x, accI); accI = fmaf(c2.w, zq.y, accI);
        }
        sPart[tid] = make_float2(accR, accI);
    }
    __syncthreads();

    // ---- Final fused reduce + head (warp 0, shuffle; no trailing barrier) ----
    if (tid < 32) {
        float trRe = 0.f, trIm = 0.f, t = 0.f, ab = 0.f;
        if (tid < U) {
#pragma unroll
            for (int pw = 0; pw < 12; pw++) {
                float2 p = sPart[tid*12 + pw];
                trRe += p.x; trIm += p.y;
            }
#pragma unroll
            for (int v = 0; v < 12; v++) {
                float4 lv = __ldg(g_lin + tid*12 + v);
                float2 d = up(sD[v]);
                trRe = fmaf(lv.x, d.x, trRe); trRe = fmaf(lv.z, d.y, trRe);
                trIm = fmaf(lv.y, d.x, trIm); trIm = fmaf(lv.w, d.y, trIm);
            }
            float2 cc = __ldg(g_cc + tid);
            trRe += cc.x; trIm += cc.y;
            t  = fmaxf(trRe, 0.0f);
            ab = t * sqrtf(trRe*trRe + trIm*trIm);
        }
        float s = ab;
#pragma unroll
        for (int off = 8; off >= 1; off >>= 1)
            s += __shfl_xor_sync(0xffffffffu, s, off, 16);
        float invn = 1.0f / fmaxf(s * (1.0f / U), 0.001f);
        float contrib = 0.f;
        if (tid < U) {
            float sc = t * invn * (1.0f / 3.0f);
            contrib = sc * trRe * __ldg(&dw[2*tid])
                    + sc * trIm * __ldg(&dw[2*tid + 1]);
        }
#pragma unroll
        for (int off = 8; off >= 1; off >>= 1)
            contrib += __shfl_xor_sync(0xffffffffu, contrib, off, 16);
        if (tid == 0) out[point] = contrib + __ldg(&db[0]);
    }
}

extern "C" void kernel_launch(void* const* d_in, const int* in_sizes, int n_in,
                              void* d_out, int out_size)
{
    const float* x  = (const float*)d_in[0];
    const float* w1 = (const float*)d_in[1];
    const float* w2 = (const float*)d_in[2];
    const float* dw = (const float*)d_in[3];
    const float* db = (const float*)d_in[4];
    float* out = (float*)d_out;

    int points = in_sizes[0] / NPTF;   // 8192

    prep_w<<<4, 512>>>(w1, w2);
    gebl_kernel<<<points, NT>>>(x, dw, db, out);
}